// round 11
// baseline (speedup 1.0000x reference)
#include <cuda_runtime.h>

#define L 4096
#define DM 1024

typedef unsigned long long u64;

__device__ __forceinline__ u64 fma2(u64 a, u64 b, u64 c) {
    u64 d; asm("fma.rn.f32x2 %0, %1, %2, %3;" : "=l"(d) : "l"(a), "l"(b), "l"(c)); return d;
}
__device__ __forceinline__ u64 add2(u64 a, u64 b) {
    u64 d; asm("add.rn.f32x2 %0, %1, %2;" : "=l"(d) : "l"(a), "l"(b)); return d;
}
__device__ __forceinline__ u64 mul2(u64 a, u64 b) {
    u64 d; asm("mul.rn.f32x2 %0, %1, %2;" : "=l"(d) : "l"(a), "l"(b)); return d;
}
__device__ __forceinline__ u64 dup2(float x) {
    u64 d; asm("mov.b64 %0, {%1, %1};" : "=l"(d) : "f"(x)); return d;
}
__device__ __forceinline__ float hsum2(u64 a) {
    float lo, hi; asm("mov.b64 {%0, %1}, %2;" : "=f"(lo), "=f"(hi) : "l"(a)); return lo + hi;
}
__device__ __forceinline__ u64 sub2(u64 a, u64 b, u64 mOne) { return fma2(mOne, b, a); }

// ---- static device scratch ----
__device__ float g_tab[1152 * 128];        // rows > 1024 are zero
__device__ float g_part1[9 * 256 * DM];    // forward DFT split partials (9 slabs)
__device__ float g_Fq[256 * DM];
__device__ float g_part2[8 * 256 * DM];
__device__ float g_CS[256 * DM];
__device__ float g_CS2[256 * DM];

__device__ __forceinline__ int drow(int d) {
    int g = d >> 4, i = d & 15;
    return ((g & 1)) + 2 * i + ((g >> 1) * 32);
}

__global__ void k0_basis() {
    int t = blockIdx.x;                 // 0..1151
    int i = threadIdx.x;                // 0..31
    float* row = &g_tab[(size_t)t * 128];
    int off = (i < 16) ? 2 * i : 32 + 2 * (i - 16);
    if (t > 1024) {
        row[off] = row[off + 1] = 0.f;
        row[64 + off] = row[64 + off + 1] = 0.f;
        return;
    }
    int k = (i < 16) ? 2 * i : 2 * (i - 16) + 1;
    int m = (k * t) & (L - 1);
    float s, c;
    sincospif((float)m / 2048.0f, &s, &c);
    row[off] = c;      row[off + 1] = c;
    row[64 + off] = s; row[64 + off + 1] = s;
}

// K1: folded forward DFT. 9 chunks x 128 t (2 substages of 64).
__global__ void __launch_bounds__(128) k1_fwd(const float* __restrict__ qf) {
    __shared__ __align__(16) float sm[64 * 128];
    int cblk = blockIdx.x, chunk = blockIdx.y, b = blockIdx.z;   // chunk 0..8
    int tid = threadIdx.x;
    int cp = cblk * 128 + tid;
    u64 acc[64];
#pragma unroll
    for (int i = 0; i < 64; i++) acc[i] = 0ull;
    const u64 mOne = dup2(-1.0f);
    const u64 half2 = dup2(0.5f);
    const u64* qp = (const u64*)qf + (size_t)b * L * 512 + cp;

    for (int sub = 0; sub < 2; sub++) {
        int t0 = chunk * 128 + sub * 64;
        const float4* src = (const float4*)&g_tab[(size_t)t0 * 128];
        float4* dst = (float4*)sm;
#pragma unroll
        for (int i = 0; i < 16; i++) dst[tid + i * 128] = src[tid + i * 128];
        __syncthreads();

        u64 n0 = qp[(size_t)t0 * 512];
        u64 n1 = qp[(size_t)((2048 - t0) & 4095) * 512];
        u64 n2 = qp[(size_t)((2048 + t0) & 4095) * 512];
        u64 n3 = qp[(size_t)((4096 - t0) & 4095) * 512];

        for (int tq = 0; tq < 64; tq++) {
            int t = t0 + tq;
            u64 c0 = n0, c1 = n1, c2 = n2, c3 = n3;
            if (tq < 63) {
                int tn = t + 1;
                n0 = qp[(size_t)(tn & 4095) * 512];
                n1 = qp[(size_t)((2048 - tn) & 4095) * 512];
                n2 = qp[(size_t)((2048 + tn) & 4095) * 512];
                n3 = qp[(size_t)((4096 - tn) & 4095) * 512];
            }
            u64 s03 = add2(c0, c3), d03 = sub2(c0, c3, mOne);
            u64 s12 = add2(c1, c2), d21 = sub2(c2, c1, mOne);
            u64 f[4];
            f[0] = add2(s03, s12);
            f[1] = sub2(s03, s12, mOne);
            f[2] = add2(d03, d21);
            f[3] = sub2(d03, d21, mOne);
            if (t == 0 || t == 1024) {
                f[0] = mul2(f[0], half2); f[1] = mul2(f[1], half2);
                f[2] = mul2(f[2], half2); f[3] = mul2(f[3], half2);
            }
            const ulonglong2* row = (const ulonglong2*)&sm[tq * 128];
#pragma unroll
            for (int j = 0; j < 32; j++) {
                ulonglong2 w = row[j];
                u64 fv = f[j >> 3];
                acc[2 * j]     = fma2(w.x, fv, acc[2 * j]);
                acc[2 * j + 1] = fma2(w.y, fv, acc[2 * j + 1]);
            }
        }
        __syncthreads();
    }
    u64* outp = (u64*)g_part1 + (size_t)chunk * 256 * 512 + (size_t)b * 64 * 512 + cp;
#pragma unroll
    for (int d = 0; d < 64; d++) outp[(size_t)drow(d) * 512] = acc[d];
}

__global__ void k1_reduce() {
    int i = blockIdx.x * blockDim.x + threadIdx.x;   // 65536 float4
    const float4* p = (const float4*)g_part1;
    float4 a = make_float4(0.f, 0.f, 0.f, 0.f);
#pragma unroll
    for (int ch = 0; ch < 9; ch++) {
        float4 v = p[(size_t)ch * 65536 + i];
        a.x += v.x; a.y += v.y; a.z += v.z; a.w += v.w;
    }
    ((float4*)g_Fq)[i] = a;
}

// GEMM v5: f32x2 over reduction axis c (measured-best v1) with conflict-free
// strided j assignment (j = jj*16 + tx) and 4 CTAs/SM.
// part2[kc][r][j] = sum_{c in 128-slab kc} A[r][c] * W[j][c]
__global__ void __launch_bounds__(128, 4) k_gemm(const float* __restrict__ W, int phase) {
    __shared__ float sA[64][66];
    __shared__ float sW[64][66];
    const float* A = (phase == 0) ? g_Fq : g_CS;
    int jb = blockIdx.x, rb = blockIdx.y, kc = blockIdx.z;   // 16, 4, 8
    int tid = threadIdx.x;
    int tx = tid & 15, ty = tid >> 4;        // tx -> 4 strided j, ty -> 8 r
    u64 acc[8][4];
#pragma unroll
    for (int r = 0; r < 8; r++)
#pragma unroll
        for (int j = 0; j < 4; j++) acc[r][j] = 0ull;

    for (int ss = 0; ss < 2; ss++) {
        int c0 = kc * 128 + ss * 64;
        for (int i = tid; i < 1024; i += 128) {
            int r = i >> 4, q4 = (i & 15) * 4;
            float4 v = *(const float4*)&A[(size_t)(rb * 64 + r) * DM + c0 + q4];
            sA[r][q4] = v.x; sA[r][q4 + 1] = v.y; sA[r][q4 + 2] = v.z; sA[r][q4 + 3] = v.w;
        }
        for (int i = tid; i < 1024; i += 128) {
            int j = i >> 4, q4 = (i & 15) * 4;
            float4 v = *(const float4*)&W[(size_t)(jb * 64 + j) * DM + c0 + q4];
            sW[j][q4] = v.x; sW[j][q4 + 1] = v.y; sW[j][q4 + 2] = v.z; sW[j][q4 + 3] = v.w;
        }
        __syncthreads();
#pragma unroll 8
        for (int cc2 = 0; cc2 < 32; cc2++) {
            u64 wv[4], av[8];
#pragma unroll
            for (int jj = 0; jj < 4; jj++) wv[jj] = *(const u64*)&sW[jj * 16 + tx][cc2 * 2];
#pragma unroll
            for (int rr = 0; rr < 8; rr++) av[rr] = *(const u64*)&sA[ty * 8 + rr][cc2 * 2];
#pragma unroll
            for (int rr = 0; rr < 8; rr++)
#pragma unroll
                for (int jj = 0; jj < 4; jj++) acc[rr][jj] = fma2(av[rr], wv[jj], acc[rr][jj]);
        }
        __syncthreads();
    }
#pragma unroll
    for (int rr = 0; rr < 8; rr++) {
        size_t base = (size_t)kc * 262144 + (size_t)(rb * 64 + ty * 8 + rr) * DM + jb * 64;
#pragma unroll
        for (int jj = 0; jj < 4; jj++)
            g_part2[base + jj * 16 + tx] = hsum2(acc[rr][jj]);
    }
}

__global__ void k_mix(const float* __restrict__ bv, const float* __restrict__ wr_,
                      const float* __restrict__ wi_) {
    int n = blockIdx.x * blockDim.x + threadIdx.x;
    int j = n & 1023, k = (n >> 10) & 31, b = n >> 15;
    int rC = b * 64 + k, rS = rC + 32;
    float C = 0.f, S = 0.f;
#pragma unroll
    for (int kc = 0; kc < 8; kc++) {
        C += g_part2[(size_t)kc * 262144 + (size_t)rC * DM + j];
        S += g_part2[(size_t)kc * 262144 + (size_t)rS * DM + j];
    }
    if (k == 0) C += 4096.0f * bv[j];
    int h = j >> 6, d = j & 63;
    float wr = wr_[(h * 32 + k) * 64 + d];
    float wi = wi_[(h * 32 + k) * 64 + d];
    float a = (k == 0 ? 1.0f : 2.0f) * (1.0f / 4096.0f);
    g_CS[(size_t)rC * DM + j] = a * (C * wr + S * wi);
    g_CS[(size_t)rS * DM + j] = a * (S * wr - C * wi);
}

__global__ void k5_reduce() {
    int i = blockIdx.x * blockDim.x + threadIdx.x;
    const float4* p = (const float4*)g_part2;
    float4 a = make_float4(0.f, 0.f, 0.f, 0.f);
#pragma unroll
    for (int kc = 0; kc < 8; kc++) {
        float4 v = p[(size_t)kc * 65536 + i];
        a.x += v.x; a.y += v.y; a.z += v.z; a.w += v.w;
    }
    ((float4*)g_CS2)[i] = a;
}

// K4: folded expansion. 9 chunks x 128 t (2 substages); cs loaded once per block.
__global__ void __launch_bounds__(128) k4_exp(float* __restrict__ outf, const float* __restrict__ bo) {
    __shared__ __align__(16) float sm[64 * 128];
    int cblk = blockIdx.x, chunk = blockIdx.y, b = blockIdx.z;   // chunk 0..8
    int tid = threadIdx.x;
    int cp = cblk * 128 + tid;
    const u64 mOne = dup2(-1.0f);
    u64 cs[64];
    const u64* csp = (const u64*)g_CS2 + (size_t)b * 64 * 512 + cp;
#pragma unroll
    for (int d = 0; d < 64; d++) cs[d] = csp[(size_t)drow(d) * 512];
    u64 bo2 = ((const u64*)bo)[cp];
    u64* outp = (u64*)outf + (size_t)b * L * 512 + cp;

    for (int sub = 0; sub < 2; sub++) {
        int t0 = chunk * 128 + sub * 64;
        const float4* src = (const float4*)&g_tab[(size_t)t0 * 128];
        float4* dst = (float4*)sm;
#pragma unroll
        for (int i = 0; i < 16; i++) dst[tid + i * 128] = src[tid + i * 128];
        __syncthreads();

        for (int tq = 0; tq < 64; tq++) {
            int t = t0 + tq;
            const ulonglong2* row = (const ulonglong2*)&sm[tq * 128];
            u64 A0 = 0, A1 = 0, A2 = 0, A3 = 0;
#pragma unroll
            for (int j = 0; j < 32; j++) {
                ulonglong2 w = row[j];
                if ((j >> 3) == 0) { A0 = fma2(w.x, cs[2 * j], A0); A0 = fma2(w.y, cs[2 * j + 1], A0); }
                else if ((j >> 3) == 1) { A1 = fma2(w.x, cs[2 * j], A1); A1 = fma2(w.y, cs[2 * j + 1], A1); }
                else if ((j >> 3) == 2) { A2 = fma2(w.x, cs[2 * j], A2); A2 = fma2(w.y, cs[2 * j + 1], A2); }
                else { A3 = fma2(w.x, cs[2 * j], A3); A3 = fma2(w.y, cs[2 * j + 1], A3); }
            }
            if (t <= 1024) {
                u64 u = add2(add2(A0, A1), bo2);
                u64 v = add2(sub2(A0, A1, mOne), bo2);
                u64 w_ = add2(A2, A3);
                u64 x = sub2(A2, A3, mOne);
                outp[(size_t)t * 512]                    = add2(u, w_);
                outp[(size_t)(2048 - t) * 512]           = sub2(v, x, mOne);
                outp[(size_t)(2048 + t) * 512]           = add2(v, x);
                outp[(size_t)((4096 - t) & 4095) * 512]  = sub2(u, w_, mOne);
            }
        }
        __syncthreads();
    }
}

extern "C" void kernel_launch(void* const* d_in, const int* in_sizes, int n_in,
                              void* d_out, int out_size) {
    const float* q  = (const float*)d_in[0];
    const float* Wv = (const float*)d_in[1];
    const float* bv = (const float*)d_in[2];
    const float* Wo = (const float*)d_in[3];
    const float* bo = (const float*)d_in[4];
    const float* wr = (const float*)d_in[5];
    const float* wi = (const float*)d_in[6];
    float* out = (float*)d_out;

    k0_basis<<<1152, 32>>>();
    k1_fwd<<<dim3(4, 9, 4), 128>>>(q);
    k1_reduce<<<256, 256>>>();
    k_gemm<<<dim3(16, 4, 8), 128>>>(Wv, 0);
    k_mix<<<512, 256>>>(bv, wr, wi);
    k_gemm<<<dim3(16, 4, 8), 128>>>(Wo, 1);
    k5_reduce<<<256, 256>>>();
    k4_exp<<<dim3(4, 9, 4), 128>>>(out, bo);
}

// round 12
// speedup vs baseline: 1.4860x; 1.4860x over previous
#include <cuda_runtime.h>

#define L 4096
#define DM 1024

typedef unsigned long long u64;

__device__ __forceinline__ u64 fma2(u64 a, u64 b, u64 c) {
    u64 d; asm("fma.rn.f32x2 %0, %1, %2, %3;" : "=l"(d) : "l"(a), "l"(b), "l"(c)); return d;
}
__device__ __forceinline__ u64 add2(u64 a, u64 b) {
    u64 d; asm("add.rn.f32x2 %0, %1, %2;" : "=l"(d) : "l"(a), "l"(b)); return d;
}
__device__ __forceinline__ u64 mul2(u64 a, u64 b) {
    u64 d; asm("mul.rn.f32x2 %0, %1, %2;" : "=l"(d) : "l"(a), "l"(b)); return d;
}
__device__ __forceinline__ u64 dup2(float x) {
    u64 d; asm("mov.b64 %0, {%1, %1};" : "=l"(d) : "f"(x)); return d;
}
__device__ __forceinline__ float hsum2(u64 a) {
    float lo, hi; asm("mov.b64 {%0, %1}, %2;" : "=f"(lo), "=f"(hi) : "l"(a)); return lo + hi;
}
__device__ __forceinline__ u64 sub2(u64 a, u64 b, u64 mOne) { return fma2(mOne, b, a); }

// ---- static device scratch ----
__device__ float g_tab[1088 * 128];
__device__ float g_part1[17 * 256 * DM];
__device__ float g_Fq[256 * DM];
__device__ float g_part2[8 * 256 * DM];
__device__ float g_CS[256 * DM];
__device__ float g_CS2[256 * DM];

__device__ __forceinline__ int drow(int d) {
    int g = d >> 4, i = d & 15;
    return ((g & 1)) + 2 * i + ((g >> 1) * 32);
}

__global__ void k0_basis() {
    int t = blockIdx.x;
    int i = threadIdx.x;
    float* row = &g_tab[(size_t)t * 128];
    int off = (i < 16) ? 2 * i : 32 + 2 * (i - 16);
    if (t > 1024) {
        row[off] = row[off + 1] = 0.f;
        row[64 + off] = row[64 + off + 1] = 0.f;
        return;
    }
    int k = (i < 16) ? 2 * i : 2 * (i - 16) + 1;
    int m = (k * t) & (L - 1);
    float s, c;
    sincospif((float)m / 2048.0f, &s, &c);
    row[off] = c;      row[off + 1] = c;
    row[64 + off] = s; row[64 + off + 1] = s;
}

// K1: folded forward DFT (R3/R4 measured-best config: 64-t chunks, grid 272)
__global__ void __launch_bounds__(128) k1_fwd(const float* __restrict__ qf) {
    __shared__ __align__(16) float sm[64 * 128];
    int cblk = blockIdx.x, chunk = blockIdx.y, b = blockIdx.z;
    int tid = threadIdx.x;
    int cp = cblk * 128 + tid;
    u64 acc[64];
#pragma unroll
    for (int i = 0; i < 64; i++) acc[i] = 0ull;
    const u64 mOne = dup2(-1.0f);
    const u64 half2 = dup2(0.5f);
    const u64* qp = (const u64*)qf + (size_t)b * L * 512 + cp;
    int t0 = chunk * 64;

    const float4* src = (const float4*)&g_tab[(size_t)t0 * 128];
    float4* dst = (float4*)sm;
#pragma unroll
    for (int i = 0; i < 16; i++) dst[tid + i * 128] = src[tid + i * 128];
    __syncthreads();

    u64 n0 = qp[(size_t)t0 * 512];
    u64 n1 = qp[(size_t)(2048 - t0) * 512];
    u64 n2 = qp[(size_t)(2048 + t0) * 512];
    u64 n3 = qp[(size_t)((4096 - t0) & 4095) * 512];

    for (int tq = 0; tq < 64; tq++) {
        int t = t0 + tq;
        u64 c0 = n0, c1 = n1, c2 = n2, c3 = n3;
        if (tq < 63) {
            int tn = t + 1;
            n0 = qp[(size_t)tn * 512];
            n1 = qp[(size_t)(2048 - tn) * 512];
            n2 = qp[(size_t)(2048 + tn) * 512];
            n3 = qp[(size_t)((4096 - tn) & 4095) * 512];
        }
        u64 s03 = add2(c0, c3), d03 = sub2(c0, c3, mOne);
        u64 s12 = add2(c1, c2), d21 = sub2(c2, c1, mOne);
        u64 f[4];
        f[0] = add2(s03, s12);
        f[1] = sub2(s03, s12, mOne);
        f[2] = add2(d03, d21);
        f[3] = sub2(d03, d21, mOne);
        if (t == 0 || t == 1024) {
            f[0] = mul2(f[0], half2); f[1] = mul2(f[1], half2);
            f[2] = mul2(f[2], half2); f[3] = mul2(f[3], half2);
        }
        const ulonglong2* row = (const ulonglong2*)&sm[tq * 128];
#pragma unroll
        for (int j = 0; j < 32; j++) {
            ulonglong2 w = row[j];
            u64 fv = f[j >> 3];
            acc[2 * j]     = fma2(w.x, fv, acc[2 * j]);
            acc[2 * j + 1] = fma2(w.y, fv, acc[2 * j + 1]);
        }
    }
    u64* outp = (u64*)g_part1 + (size_t)chunk * 256 * 512 + (size_t)b * 64 * 512 + cp;
#pragma unroll
    for (int d = 0; d < 64; d++) outp[(size_t)drow(d) * 512] = acc[d];
}

__global__ void k1_reduce() {
    int i = blockIdx.x * blockDim.x + threadIdx.x;
    const float4* p = (const float4*)g_part1;
    float4 a = make_float4(0.f, 0.f, 0.f, 0.f);
#pragma unroll
    for (int ch = 0; ch < 17; ch++) {
        float4 v = p[(size_t)ch * 65536 + i];
        a.x += v.x; a.y += v.y; a.z += v.z; a.w += v.w;
    }
    ((float4*)g_Fq)[i] = a;
}

// GEMM v5 (R11 measured: 21.5us): f32x2 over c, strided conflict-free j.
__global__ void __launch_bounds__(128, 4) k_gemm(const float* __restrict__ W, int phase) {
    __shared__ float sA[64][66];
    __shared__ float sW[64][66];
    const float* A = (phase == 0) ? g_Fq : g_CS;
    int jb = blockIdx.x, rb = blockIdx.y, kc = blockIdx.z;   // 16, 4, 8
    int tid = threadIdx.x;
    int tx = tid & 15, ty = tid >> 4;
    u64 acc[8][4];
#pragma unroll
    for (int r = 0; r < 8; r++)
#pragma unroll
        for (int j = 0; j < 4; j++) acc[r][j] = 0ull;

    for (int ss = 0; ss < 2; ss++) {
        int c0 = kc * 128 + ss * 64;
        for (int i = tid; i < 1024; i += 128) {
            int r = i >> 4, q4 = (i & 15) * 4;
            float4 v = *(const float4*)&A[(size_t)(rb * 64 + r) * DM + c0 + q4];
            sA[r][q4] = v.x; sA[r][q4 + 1] = v.y; sA[r][q4 + 2] = v.z; sA[r][q4 + 3] = v.w;
        }
        for (int i = tid; i < 1024; i += 128) {
            int j = i >> 4, q4 = (i & 15) * 4;
            float4 v = *(const float4*)&W[(size_t)(jb * 64 + j) * DM + c0 + q4];
            sW[j][q4] = v.x; sW[j][q4 + 1] = v.y; sW[j][q4 + 2] = v.z; sW[j][q4 + 3] = v.w;
        }
        __syncthreads();
#pragma unroll 8
        for (int cc2 = 0; cc2 < 32; cc2++) {
            u64 wv[4], av[8];
#pragma unroll
            for (int jj = 0; jj < 4; jj++) wv[jj] = *(const u64*)&sW[jj * 16 + tx][cc2 * 2];
#pragma unroll
            for (int rr = 0; rr < 8; rr++) av[rr] = *(const u64*)&sA[ty * 8 + rr][cc2 * 2];
#pragma unroll
            for (int rr = 0; rr < 8; rr++)
#pragma unroll
                for (int jj = 0; jj < 4; jj++) acc[rr][jj] = fma2(av[rr], wv[jj], acc[rr][jj]);
        }
        __syncthreads();
    }
#pragma unroll
    for (int rr = 0; rr < 8; rr++) {
        size_t base = (size_t)kc * 262144 + (size_t)(rb * 64 + ty * 8 + rr) * DM + jb * 64;
#pragma unroll
        for (int jj = 0; jj < 4; jj++)
            g_part2[base + jj * 16 + tx] = hsum2(acc[rr][jj]);
    }
}

__global__ void k_mix(const float* __restrict__ bv, const float* __restrict__ wr_,
                      const float* __restrict__ wi_) {
    int n = blockIdx.x * blockDim.x + threadIdx.x;
    int j = n & 1023, k = (n >> 10) & 31, b = n >> 15;
    int rC = b * 64 + k, rS = rC + 32;
    float C = 0.f, S = 0.f;
#pragma unroll
    for (int kc = 0; kc < 8; kc++) {
        C += g_part2[(size_t)kc * 262144 + (size_t)rC * DM + j];
        S += g_part2[(size_t)kc * 262144 + (size_t)rS * DM + j];
    }
    if (k == 0) C += 4096.0f * bv[j];
    int h = j >> 6, d = j & 63;
    float wr = wr_[(h * 32 + k) * 64 + d];
    float wi = wi_[(h * 32 + k) * 64 + d];
    float a = (k == 0 ? 1.0f : 2.0f) * (1.0f / 4096.0f);
    g_CS[(size_t)rC * DM + j] = a * (C * wr + S * wi);
    g_CS[(size_t)rS * DM + j] = a * (S * wr - C * wi);
}

__global__ void k5_reduce() {
    int i = blockIdx.x * blockDim.x + threadIdx.x;
    const float4* p = (const float4*)g_part2;
    float4 a = make_float4(0.f, 0.f, 0.f, 0.f);
#pragma unroll
    for (int kc = 0; kc < 8; kc++) {
        float4 v = p[(size_t)kc * 65536 + i];
        a.x += v.x; a.y += v.y; a.z += v.z; a.w += v.w;
    }
    ((float4*)g_CS2)[i] = a;
}

// K4: folded expansion (R3/R4 measured-best config: 64-t chunks, grid 272)
__global__ void __launch_bounds__(128) k4_exp(float* __restrict__ outf, const float* __restrict__ bo) {
    __shared__ __align__(16) float sm[64 * 128];
    int cblk = blockIdx.x, chunk = blockIdx.y, b = blockIdx.z;
    int tid = threadIdx.x;
    int cp = cblk * 128 + tid;
    const u64 mOne = dup2(-1.0f);
    u64 cs[64];
    const u64* csp = (const u64*)g_CS2 + (size_t)b * 64 * 512 + cp;
#pragma unroll
    for (int d = 0; d < 64; d++) cs[d] = csp[(size_t)drow(d) * 512];
    u64 bo2 = ((const u64*)bo)[cp];
    u64* outp = (u64*)outf + (size_t)b * L * 512 + cp;
    int t0 = chunk * 64;

    const float4* src = (const float4*)&g_tab[(size_t)t0 * 128];
    float4* dst = (float4*)sm;
#pragma unroll
    for (int i = 0; i < 16; i++) dst[tid + i * 128] = src[tid + i * 128];
    __syncthreads();

    for (int tq = 0; tq < 64; tq++) {
        int t = t0 + tq;
        const ulonglong2* row = (const ulonglong2*)&sm[tq * 128];
        u64 A0 = 0, A1 = 0, A2 = 0, A3 = 0;
#pragma unroll
        for (int j = 0; j < 32; j++) {
            ulonglong2 w = row[j];
            if ((j >> 3) == 0) { A0 = fma2(w.x, cs[2 * j], A0); A0 = fma2(w.y, cs[2 * j + 1], A0); }
            else if ((j >> 3) == 1) { A1 = fma2(w.x, cs[2 * j], A1); A1 = fma2(w.y, cs[2 * j + 1], A1); }
            else if ((j >> 3) == 2) { A2 = fma2(w.x, cs[2 * j], A2); A2 = fma2(w.y, cs[2 * j + 1], A2); }
            else { A3 = fma2(w.x, cs[2 * j], A3); A3 = fma2(w.y, cs[2 * j + 1], A3); }
        }
        if (t <= 1024) {
            u64 u = add2(add2(A0, A1), bo2);
            u64 v = add2(sub2(A0, A1, mOne), bo2);
            u64 w_ = add2(A2, A3);
            u64 x = sub2(A2, A3, mOne);
            outp[(size_t)t * 512]                    = add2(u, w_);
            outp[(size_t)(2048 - t) * 512]           = sub2(v, x, mOne);
            outp[(size_t)(2048 + t) * 512]           = add2(v, x);
            outp[(size_t)((4096 - t) & 4095) * 512]  = sub2(u, w_, mOne);
        }
    }
}

extern "C" void kernel_launch(void* const* d_in, const int* in_sizes, int n_in,
                              void* d_out, int out_size) {
    const float* q  = (const float*)d_in[0];
    const float* Wv = (const float*)d_in[1];
    const float* bv = (const float*)d_in[2];
    const float* Wo = (const float*)d_in[3];
    const float* bo = (const float*)d_in[4];
    const float* wr = (const float*)d_in[5];
    const float* wi = (const float*)d_in[6];
    float* out = (float*)d_out;

    k0_basis<<<1088, 32>>>();
    k1_fwd<<<dim3(4, 17, 4), 128>>>(q);
    k1_reduce<<<256, 256>>>();
    k_gemm<<<dim3(16, 4, 8), 128>>>(Wv, 0);
    k_mix<<<512, 256>>>(bv, wr, wi);
    k_gemm<<<dim3(16, 4, 8), 128>>>(Wo, 1);
    k5_reduce<<<256, 256>>>();
    k4_exp<<<dim3(4, 17, 4), 128>>>(out, bo);
}